// round 5
// baseline (speedup 1.0000x reference)
#include <cuda_runtime.h>

// AlarmworkRNN collapsed to a vector RNN (only sequence row 2047 matters).
// Round 5: critical loop minimized.
//   k1: U = x_row @ W_in + b (both layers), parallel GEMM
//   k2: persistent recurrence, K=1024, state exchanged via L2, warp 14 owns
//       reduce/tanh/publish/barrier; z1 history written to g_hist
//   k3: out = tanh(hist @ W_out + b_out), parallel GEMM

#define GRID  128
#define BLOCK 512
#define NSTEP 256

__device__ unsigned g_arrive;
__device__ float g_U[2][NSTEP][1024];     // u1/u2 per step (bias folded in)
__device__ float g_hist[NSTEP][1024];     // z1(t+1) published at slot t
__device__ float g_z12[2][1024];          // parity-buffered z1+z2
__device__ float g_z2b[2][1024];          // parity-buffered z2

__global__ void rnn_init_kernel() {
    int tid = threadIdx.x;
    if (tid == 0) g_arrive = 0u;
    // buffers for iteration 0 must be zero every launch (graph replays)
    for (int j = tid; j < 1024; j += blockDim.x) {
        g_z12[0][j] = 0.0f;
        g_z2b[0][j] = 0.0f;
    }
}

__device__ __forceinline__ void arrive_release(unsigned* p) {
    asm volatile("red.release.gpu.global.add.u32 [%0], %1;"
                 :: "l"(p), "r"(1u) : "memory");
}
__device__ __forceinline__ unsigned ld_acquire_gpu(unsigned* p) {
    unsigned v;
    asm volatile("ld.acquire.gpu.global.u32 %0, [%1];"
                 : "=r"(v) : "l"(p) : "memory");
    return v;
}
__device__ __forceinline__ float4 ldcg4(const float4* p) {
    float4 u;
    asm volatile("ld.global.cg.v4.f32 {%0,%1,%2,%3}, [%4];"
                 : "=f"(u.x), "=f"(u.y), "=f"(u.z), "=f"(u.w)
                 : "l"(p) : "memory");
    return u;
}

// ---- k1: U[m][t][j] = sum_k x[t,2047,k] * W_in_m[k][j] + b_m[j] ----
// grid = 128: m = b>>6, jt = (b>>4)&3 (256-wide), tt = b&15 (16 steps)
__global__ __launch_bounds__(256)
void u_kernel(const float* __restrict__ x,
              const float* __restrict__ W_in1, const float* __restrict__ b_in1,
              const float* __restrict__ W_in2, const float* __restrict__ b_in2)
{
    __shared__ float xs[16][256];
    const int b = blockIdx.x;
    const int m  = b >> 6;
    const int jt = (b >> 4) & 3;
    const int tt = b & 15;
    const float* W  = m ? W_in2 : W_in1;
    const float* bi = m ? b_in2 : b_in1;
    const int tid = threadIdx.x;
    const int t0 = tt * 16;

    for (int i = tid; i < 16 * 256; i += 256) {
        int tr = i >> 8, k = i & 255;
        xs[tr][k] = x[((size_t)(t0 + tr) * 2048 + 2047) * 256 + k];
    }
    __syncthreads();

    const int j = jt * 256 + tid;
    float acc[16];
    const float bj = bi[j];
    #pragma unroll
    for (int r = 0; r < 16; r++) acc[r] = bj;
    #pragma unroll 4
    for (int k = 0; k < 256; k++) {
        float w = W[k * 1024 + j];
        #pragma unroll
        for (int r = 0; r < 16; r++) acc[r] += xs[r][k] * w;
    }
    #pragma unroll
    for (int r = 0; r < 16; r++) g_U[m][t0 + r][j] = acc[r];
}

// ---- k3: out[t][o] = tanh(sum_j hist[t][j] * W_out[j][o] + b_out[o]) ----
// grid = 64: 4 steps per block
__global__ __launch_bounds__(256)
void out_kernel(const float* __restrict__ W_out,
                const float* __restrict__ b_out,
                float* __restrict__ out)
{
    __shared__ float zs[4][1024];
    const int t0 = blockIdx.x * 4;
    const int tid = threadIdx.x;
    for (int i = tid; i < 4 * 1024; i += 256)
        zs[i >> 10][i & 1023] = g_hist[t0 + (i >> 10)][i & 1023];
    __syncthreads();

    float acc[4];
    const float bo = b_out[tid];
    #pragma unroll
    for (int r = 0; r < 4; r++) acc[r] = bo;
    #pragma unroll 4
    for (int jj = 0; jj < 1024; jj++) {
        float w = W_out[jj * 256 + tid];
        #pragma unroll
        for (int r = 0; r < 4; r++) acc[r] += zs[r][jj] * w;
    }
    #pragma unroll
    for (int r = 0; r < 4; r++)
        out[(size_t)(t0 + r) * 256 + tid] = tanhf(acc[r]);
}

// ---- k2: persistent recurrence ----
__global__ __launch_bounds__(BLOCK, 1)
void rnn_main_kernel(const float* __restrict__ W_rec1,
                     const float* __restrict__ W_rec2)
{
    __shared__ float redp[2][16 * 8];   // [parity][output 0..15][w8]
    __shared__ float stage[8 * 1024];   // weight staging (preload only)

    const int tid  = threadIdx.x;
    const int warp = tid >> 5;
    const int lane = tid & 31;
    const int j0   = blockIdx.x * 8;

    const int role = warp >> 3;         // 0: z1 warps 0-7, 1: z2 warps 8-15
    const int w8   = warp & 7;          // 128-wide K slice index
    const int o_l  = lane >> 2;         // output 0..7
    const int g_l  = lane & 3;          // 32-wide k-subchunk

    // ---- weight preload: wreg[32] = W_rec[k in slice][j0+o_l] ----
    float wreg[32];
    for (int round = 0; round < 2; round++) {
        const float* W = round ? W_rec2 : W_rec1;
        for (int idx = tid; idx < 8 * 1024; idx += BLOCK) {
            int k = idx >> 3, o = idx & 7;
            stage[o * 1024 + k] = W[k * 1024 + j0 + o];
        }
        __syncthreads();
        if (role == round) {
            const float4* src = (const float4*)(stage + o_l * 1024 + w8 * 128 + g_l * 32);
            #pragma unroll
            for (int c = 0; c < 8; c++) {
                float4 q = src[c];
                wreg[4*c+0] = q.x; wreg[4*c+1] = q.y;
                wreg[4*c+2] = q.z; wreg[4*c+3] = q.w;
            }
        }
        __syncthreads();
    }

    const bool isPub = (warp == 14);
    const int  ol    = lane >> 1;        // pub-warp: output index 0..15
    const bool evenL = !(lane & 1);
    float z2reg = 0.0f;                  // pub-warp lanes 16+: held z2 value
    float ureg  = 0.0f;                  // prefetched U[i][j0+...]
    if (isPub && evenL)
        ureg = g_U[(ol >= 8) ? 1 : 0][0][j0 + (ol & 7)];

    const int koff = w8 * 128 + g_l * 32;

    for (int i = 0; i < NSTEP; i++) {
        const int par = i & 1;
        const int pw  = par ^ 1;

        // GEMV: state slice straight into registers via L2
        if (role == 0 || (i & 1) == 0) {
            const float* base = (role == 0) ? g_z12[par] : g_z2b[par];
            const float4* ev = (const float4*)(base + koff);
            float a0 = 0.0f, a1 = 0.0f;
            #pragma unroll
            for (int c = 0; c < 8; c++) {
                float4 q = ldcg4(ev + c);
                a0 += wreg[4*c+0] * q.x + wreg[4*c+1] * q.y;
                a1 += wreg[4*c+2] * q.z + wreg[4*c+3] * q.w;
            }
            float acc = a0 + a1;
            acc += __shfl_xor_sync(0xffffffffu, acc, 1);
            acc += __shfl_xor_sync(0xffffffffu, acc, 2);
            if (g_l == 0) redp[par][(role * 8 + o_l) * 8 + w8] = acc;
        }
        __syncthreads();

        if (isPub) {
            // reduce 8 partials per output: lane covers half (4) of output ol
            float4 p = ((const float4*)redp[par])[lane];
            float s = p.x + p.y + p.z + p.w;
            s += __shfl_xor_sync(0xffffffffu, s, 1);   // pair total

            float val;
            if (ol < 8) {
                val = tanhf(s + ureg);                  // z1(i+1)
            } else {
                if ((i & 1) == 0) z2reg = tanhf(s + ureg);  // even i: new z2
                val = z2reg;                            // odd i: hold
            }
            // prefetch u for next step
            if (evenL && i + 1 < NSTEP)
                ureg = g_U[(ol >= 8) ? 1 : 0][i + 1][j0 + (ol & 7)];

            // z12 needs z2: even lanes <16 fetch val of lane+16
            float z2o = __shfl_sync(0xffffffffu, val, (lane + 16) & 31);
            if (evenL) {
                if (ol < 8) {
                    g_z12[pw][j0 + ol]     = val + z2o;
                    g_hist[i][j0 + ol]     = val;
                } else {
                    g_z2b[pw][j0 + ol - 8] = val;
                }
            }
            if (lane == 0 && i + 1 < NSTEP) {
                arrive_release(&g_arrive);
                const unsigned target = (unsigned)(i + 1) * GRID;
                while (ld_acquire_gpu(&g_arrive) < target) { }
            }
        }
        __syncthreads();
    }
}

extern "C" void kernel_launch(void* const* d_in, const int* in_sizes, int n_in,
                              void* d_out, int out_size) {
    (void)in_sizes; (void)n_in; (void)out_size;
    const float* x      = (const float*)d_in[0];
    const float* W_in1  = (const float*)d_in[1];
    const float* b_in1  = (const float*)d_in[2];
    const float* W_rec1 = (const float*)d_in[3];
    const float* W_in2  = (const float*)d_in[4];
    const float* b_in2  = (const float*)d_in[5];
    const float* W_rec2 = (const float*)d_in[6];
    const float* W_out  = (const float*)d_in[7];
    const float* b_out  = (const float*)d_in[8];
    float* out = (float*)d_out;

    rnn_init_kernel<<<1, 1024>>>();
    u_kernel<<<128, 256>>>(x, W_in1, b_in1, W_in2, b_in2);
    rnn_main_kernel<<<GRID, BLOCK>>>(W_rec1, W_rec2);
    out_kernel<<<64, 256>>>(W_out, b_out, out);
}